// round 4
// baseline (speedup 1.0000x reference)
#include <cuda_runtime.h>
#include <cuda_bf16.h>
#include <cstdint>

// Problem constants
#define SEQ    4096
#define DK     128
#define PLANE  (SEQ * DK)      // 524288 floats per (b,h) plane
#define PPB    2               // planes per block

// 256-bit global load/store (sm_100+). 32B alignment required.
#define LDG256_CS(r, p)                                                     \
    asm volatile("ld.global.cs.v8.b32 {%0,%1,%2,%3,%4,%5,%6,%7}, [%8];"     \
        : "=r"(r[0]), "=r"(r[1]), "=r"(r[2]), "=r"(r[3]),                   \
          "=r"(r[4]), "=r"(r[5]), "=r"(r[6]), "=r"(r[7])                    \
        : "l"(p) : "memory")

#define STG256_CS(p, r)                                                     \
    asm volatile("st.global.cs.v8.b32 [%0], {%1,%2,%3,%4,%5,%6,%7,%8};"     \
        :: "l"(p),                                                          \
           "r"(r[0]), "r"(r[1]), "r"(r[2]), "r"(r[3]),                      \
           "r"(r[4]), "r"(r[5]), "r"(r[6]), "r"(r[7]) : "memory")

// Fused: out[...,s,d] = R[d,d,s] * x[...,s,d]
// One block = 32-seq x 128-dim tile (16KB, contiguous) applied to PPB planes.
// Diag slice read straight from R into smem (L2-cached across plane-blocks).
__global__ void __launch_bounds__(256) rope_diag_kernel(
        const float* __restrict__ R,
        const float* __restrict__ x,
        float* __restrict__ out) {
    __shared__ float diag[32][132];   // row = s; 528B row stride (16B aligned)

    const unsigned s0     = blockIdx.x * 32;     // 128 s-tiles
    const unsigned plane0 = blockIdx.y * PPB;    // 64 plane-pairs
    const unsigned tid    = threadIdx.x;
    const unsigned warp   = tid >> 5;
    const unsigned lane   = tid & 31;

    // diag[s][d] = R[d*(DK+1)*SEQ + s]; coalesced 128B row reads.
    #pragma unroll
    for (int r = 0; r < 16; r++) {
        unsigned d = warp + r * 8;
        diag[lane][d] = __ldg(&R[(size_t)d * ((DK + 1) * SEQ) + s0 + lane]);
    }
    __syncthreads();

    const size_t tileBase = (size_t)blockIdx.x * 4096;   // floats into plane

    #pragma unroll
    for (int k = 0; k < 2; k++) {
        const unsigned idx8 = k * 256 + tid;     // 0..511 : 8-float chunk id
        const unsigned s    = idx8 >> 4;         // 16 chunks per s-row
        const unsigned d8   = (idx8 & 15) << 3;  // 0,8,...,120
        const size_t   off  = tileBase + (size_t)idx8 * 8;

        // Front-batch both plane loads (2 x 256-bit in flight)
        uint32_t xv[PPB][8];
        #pragma unroll
        for (int p = 0; p < PPB; p++) {
            const float* xp = x + (size_t)(plane0 + p) * PLANE + off;
            LDG256_CS(xv[p], xp);
        }

        // Diag chunk: two conflict-light LDS.128 from row s
        float4 dv0 = *reinterpret_cast<const float4*>(&diag[s][d8]);
        float4 dv1 = *reinterpret_cast<const float4*>(&diag[s][d8 + 4]);
        float dvf[8] = {dv0.x, dv0.y, dv0.z, dv0.w, dv1.x, dv1.y, dv1.z, dv1.w};

        #pragma unroll
        for (int p = 0; p < PPB; p++) {
            uint32_t rv[8];
            #pragma unroll
            for (int e = 0; e < 8; e++)
                rv[e] = __float_as_uint(__uint_as_float(xv[p][e]) * dvf[e]);
            float* op = out + (size_t)(plane0 + p) * PLANE + off;
            STG256_CS(op, rv);
        }
    }
}

extern "C" void kernel_launch(void* const* d_in, const int* in_sizes, int n_in,
                              void* d_out, int out_size) {
    const float* x = (const float*)d_in[0];
    // d_in[1] = token_positions (unused by the reference semantics)
    const float* R = (const float*)d_in[2];
    float* out = (float*)d_out;

    dim3 grid(SEQ / 32, 128 / PPB);   // (128, 64) = 8192 blocks
    rope_diag_kernel<<<grid, 256>>>(R, x, out);
    (void)in_sizes; (void)n_in; (void)out_size;
}

// round 5
// speedup vs baseline: 1.0140x; 1.0140x over previous
#include <cuda_runtime.h>
#include <cuda_bf16.h>
#include <cstdint>

// Problem constants
#define SEQ    4096
#define DK     128
#define PLANE  (SEQ * DK)      // 524288 floats per (b,h) plane
#define PLANE4 (PLANE / 4)     // 131072 float4s per plane
#define PPB    4               // planes per block (diag amortization)

// Fused kernel: out[...,s,d] = R[d,d,s] * x[...,s,d]
// One block = one 32-seq x 128-dim tile, applied to PPB planes (as 2 pairs).
// Diag slice read straight from R (coalesced, L2-cached across plane blocks)
// into smem, broadcast to the streaming multiply.
__global__ void __launch_bounds__(256) rope_diag_kernel(
        const float* __restrict__ R,
        const float4* __restrict__ x,
        float4* __restrict__ out) {
    // Padded to 132 floats/row: 16B-aligned rows -> conflict-free LDS.128
    __shared__ float diag[32][132];

    const unsigned s0     = blockIdx.x * 32;        // 128 s-tiles
    const unsigned plane0 = blockIdx.y * PPB;       // 32 plane-quads
    const unsigned tid    = threadIdx.x;
    const unsigned warp   = tid >> 5;
    const unsigned lane   = tid & 31;

    // diag[s][d] = R[d*(DK+1)*SEQ + s]; each row a coalesced 128B read.
    #pragma unroll
    for (int r = 0; r < 16; r++) {
        unsigned d = warp + r * 8;
        diag[lane][d] = __ldg(&R[(size_t)d * ((DK + 1) * SEQ) + s0 + lane]);
    }
    __syncthreads();

    const unsigned tileBase = blockIdx.x * 1024;    // float4 offset in plane

    // Pre-read this thread's 4 diag chunks once (registers, reused x4 planes)
    float4 dvv[4];
    #pragma unroll
    for (int k = 0; k < 4; k++) {
        unsigned idx = k * 256 + tid;               // 0..1023 within tile
        unsigned s   = idx >> 5;
        unsigned d4  = (idx & 31) * 4;
        dvv[k] = *reinterpret_cast<const float4*>(&diag[s][d4]);
    }

    // Process planes in pairs: 8 front-batched float4 loads per pair.
    #pragma unroll
    for (int pp = 0; pp < PPB / 2; pp++) {
        const unsigned pA = plane0 + pp * 2;

        float4 xv[2][4];
        #pragma unroll
        for (int p = 0; p < 2; p++) {
            const float4* xp = x + (size_t)(pA + p) * PLANE4 + tileBase;
            #pragma unroll
            for (int k = 0; k < 4; k++)
                xv[p][k] = __ldcs(&xp[k * 256 + tid]);
        }

        #pragma unroll
        for (int k = 0; k < 4; k++) {
            unsigned idx = k * 256 + tid;
            #pragma unroll
            for (int p = 0; p < 2; p++) {
                float4 r;
                r.x = xv[p][k].x * dvv[k].x;
                r.y = xv[p][k].y * dvv[k].y;
                r.z = xv[p][k].z * dvv[k].z;
                r.w = xv[p][k].w * dvv[k].w;
                __stcs(&out[(size_t)(pA + p) * PLANE4 + tileBase + idx], r);
            }
        }
    }
}

extern "C" void kernel_launch(void* const* d_in, const int* in_sizes, int n_in,
                              void* d_out, int out_size) {
    const float* x = (const float*)d_in[0];
    // d_in[1] = token_positions (unused by the reference semantics)
    const float* R = (const float*)d_in[2];
    float* out = (float*)d_out;

    dim3 grid(SEQ / 32, 128 / PPB);   // (128, 32) = 4096 blocks
    rope_diag_kernel<<<grid, 256>>>(R, (const float4*)x, (float4*)out);
    (void)in_sizes; (void)n_in; (void)out_size;
}

// round 6
// speedup vs baseline: 1.0163x; 1.0023x over previous
#include <cuda_runtime.h>
#include <cuda_bf16.h>
#include <cstdint>

// Problem constants
#define SEQ    4096
#define DK     128
#define PLANE  (SEQ * DK)      // 524288 floats per (b,h) plane
#define PLANE4 (PLANE / 4)     // 131072 float4s per plane
#define PPB    8               // planes per block (diag + prologue amortization)

// Fused kernel: out[...,s,d] = R[d,d,s] * x[...,s,d]
// One block = one 32-seq x 128-dim tile, applied to PPB planes (4 pairs).
// Diag slice read straight from R (coalesced, L2-cached across plane blocks)
// into smem, cached in registers, broadcast to the streaming multiply.
__global__ void __launch_bounds__(256) rope_diag_kernel(
        const float* __restrict__ R,
        const float4* __restrict__ x,
        float4* __restrict__ out) {
    // Padded to 132 floats/row: 16B-aligned rows -> conflict-free LDS.128
    __shared__ float diag[32][132];

    const unsigned s0     = blockIdx.x * 32;        // 128 s-tiles
    const unsigned plane0 = blockIdx.y * PPB;       // 16 plane-octets
    const unsigned tid    = threadIdx.x;
    const unsigned warp   = tid >> 5;
    const unsigned lane   = tid & 31;

    // diag[s][d] = R[d*(DK+1)*SEQ + s]; each row a coalesced 128B read.
    #pragma unroll
    for (int r = 0; r < 16; r++) {
        unsigned d = warp + r * 8;
        diag[lane][d] = __ldg(&R[(size_t)d * ((DK + 1) * SEQ) + s0 + lane]);
    }
    __syncthreads();

    const unsigned tileBase = blockIdx.x * 1024;    // float4 offset in plane

    // Pre-read this thread's 4 diag chunks once (16 regs, reused x8 planes)
    float4 dvv[4];
    #pragma unroll
    for (int k = 0; k < 4; k++) {
        unsigned idx = k * 256 + tid;               // 0..1023 within tile
        unsigned s   = idx >> 5;
        unsigned d4  = (idx & 31) * 4;
        dvv[k] = *reinterpret_cast<const float4*>(&diag[s][d4]);
    }

    // Process planes in pairs: 8 front-batched float4 loads per pair.
    #pragma unroll
    for (int pp = 0; pp < PPB / 2; pp++) {
        const unsigned pA = plane0 + pp * 2;

        float4 xv[2][4];
        #pragma unroll
        for (int p = 0; p < 2; p++) {
            const float4* xp = x + (size_t)(pA + p) * PLANE4 + tileBase;
            #pragma unroll
            for (int k = 0; k < 4; k++)
                xv[p][k] = __ldcs(&xp[k * 256 + tid]);
        }

        #pragma unroll
        for (int k = 0; k < 4; k++) {
            unsigned idx = k * 256 + tid;
            #pragma unroll
            for (int p = 0; p < 2; p++) {
                float4 r;
                r.x = xv[p][k].x * dvv[k].x;
                r.y = xv[p][k].y * dvv[k].y;
                r.z = xv[p][k].z * dvv[k].z;
                r.w = xv[p][k].w * dvv[k].w;
                __stcs(&out[(size_t)(pA + p) * PLANE4 + tileBase + idx], r);
            }
        }
    }
}

extern "C" void kernel_launch(void* const* d_in, const int* in_sizes, int n_in,
                              void* d_out, int out_size) {
    const float* x = (const float*)d_in[0];
    // d_in[1] = token_positions (unused by the reference semantics)
    const float* R = (const float*)d_in[2];
    float* out = (float*)d_out;

    dim3 grid(SEQ / 32, 128 / PPB);   // (128, 16) = 2048 blocks
    rope_diag_kernel<<<grid, 256>>>(R, (const float4*)x, (float4*)out);
    (void)in_sizes; (void)n_in; (void)out_size;
}